// round 14
// baseline (speedup 1.0000x reference)
#include <cuda_runtime.h>
#include <cstdint>

#define BATCH 2
#define SEQ   2048
#define CH    1024
#define NH    16
#define HD    64
#define MROWS (BATCH*SEQ)   /* 4096 */

// Scratch (allocation-free rule: __device__ globals)
__device__ float g_qkv[MROWS * 3 * CH];   // tf32-rounded qkv
__device__ float g_y  [MROWS * CH];       // tf32-rounded attn out
__device__ float g_x  [MROWS * CH];       // tf32-rounded x
__device__ float g_wqT[3 * CH * CH];      // transposed + tf32 w_qkv  [3C][C]
__device__ float g_woT[CH * CH];          // transposed + tf32 w_out  [C][C]

// ---------------------------------------------------------------------------
// TF32 / MMA / cp.async / ldmatrix helpers
// ---------------------------------------------------------------------------
__device__ __forceinline__ uint32_t to_tf32_bits(float x) {
    uint32_t y;
    asm("cvt.rna.tf32.f32 %0, %1;" : "=r"(y) : "f"(x));
    return y;
}
__device__ __forceinline__ float to_tf32(float x) {
    return __uint_as_float(to_tf32_bits(x));
}

__device__ __forceinline__ void mma_tf32(float c[4], const uint32_t a[4], const uint32_t b0, const uint32_t b1) {
    asm volatile(
        "mma.sync.aligned.m16n8k8.row.col.f32.tf32.tf32.f32 "
        "{%0,%1,%2,%3}, {%4,%5,%6,%7}, {%8,%9}, {%0,%1,%2,%3};"
        : "+f"(c[0]), "+f"(c[1]), "+f"(c[2]), "+f"(c[3])
        : "r"(a[0]), "r"(a[1]), "r"(a[2]), "r"(a[3]),
          "r"(b0), "r"(b1));
}

__device__ __forceinline__ void ldsm_x4(uint32_t r[4], uint32_t saddr) {
    asm volatile("ldmatrix.sync.aligned.m8n8.x4.shared.b16 {%0,%1,%2,%3}, [%4];"
        : "=r"(r[0]), "=r"(r[1]), "=r"(r[2]), "=r"(r[3]) : "r"(saddr));
}

__device__ __forceinline__ void cp_async16(uint32_t saddr, const void* gptr) {
    asm volatile("cp.async.cg.shared.global [%0], [%1], 16;" :: "r"(saddr), "l"(gptr));
}
__device__ __forceinline__ void cp_commit() { asm volatile("cp.async.commit_group;"); }
__device__ __forceinline__ void cp_wait0()  { asm volatile("cp.async.wait_group 0;"); }

// ---------------------------------------------------------------------------
// Elementwise tf32 rounding (float4 granularity)
// ---------------------------------------------------------------------------
__global__ void cvt_tf32_kernel(const float4* __restrict__ in, float4* __restrict__ out, int n4)
{
    int i = blockIdx.x * blockDim.x + threadIdx.x;
    if (i < n4) {
        float4 v = in[i];
        v.x = to_tf32(v.x); v.y = to_tf32(v.y);
        v.z = to_tf32(v.z); v.w = to_tf32(v.w);
        out[i] = v;
    }
}

// Transpose + tf32 round: in [R][Cc] -> out [Cc][R]
__global__ void transpose_tf32_kernel(const float* __restrict__ in, float* __restrict__ out,
                                      int R, int Cc)
{
    __shared__ float tile[32][33];
    int bx = blockIdx.x * 32;   // Cc base
    int by = blockIdx.y * 32;   // R base
    int tx = threadIdx.x, ty = threadIdx.y;
    #pragma unroll
    for (int i = 0; i < 32; i += 8)
        tile[ty + i][tx] = in[(size_t)(by + ty + i) * Cc + bx + tx];
    __syncthreads();
    #pragma unroll
    for (int i = 0; i < 32; i += 8)
        out[(size_t)(bx + ty + i) * R + by + tx] = to_tf32(tile[tx][ty + i]);
}

// ---------------------------------------------------------------------------
// TF32 tensor-core GEMM, cp.async double-buffered, BOTH operand fragments
// via ldmatrix. C = A(MxK) @ Bt^T (+bias); A [M][K], Bt [N][K].
// (identical to R13 passing kernel)
// ---------------------------------------------------------------------------
template<bool HAS_BIAS, bool ROUND_OUT>
__global__ __launch_bounds__(256, 2)
void gemm_tf32_kernel(const float* __restrict__ A, const float* __restrict__ Bt,
                      const float* __restrict__ bias, float* __restrict__ Cmat,
                      int Mx, int Nx, int Kx)
{
    constexpr int BM = 128, BK = 32;
    constexpr int STR = 36;
    constexpr int TSZ = BM * STR;            // floats per tile buffer
    extern __shared__ float smem[];
    float* Asb[2] = { smem,           smem + TSZ };
    float* Bsb[2] = { smem + 2 * TSZ, smem + 3 * TSZ };

    const int tid  = threadIdx.x;
    const int lane = tid & 31;
    const int wid  = tid >> 5;
    const int wm   = wid >> 2;
    const int wn   = wid & 3;
    const int grp  = lane >> 2;
    const int qid  = lane & 3;
    const int bm = blockIdx.y * BM;
    const int bn = blockIdx.x * BM;

    const int a_lrow = ((lane >> 3) & 1) * 8 + (lane & 7);   // A-pattern row
    const int a_lcol = (lane >> 4) * 4;
    const int b_lrow = (lane >> 4) * 8 + (lane & 7);         // B-pattern row
    const int b_lcol = ((lane >> 3) & 1) * 4;

    const int g_row = tid >> 3, g_k4 = (tid & 7) * 4;        // cp.async coords

    const float* Aptr = A  + (size_t)(bm + g_row) * Kx + g_k4;
    const float* Bptr = Bt + (size_t)(bn + g_row) * Kx + g_k4;

    uint32_t sA[2], sB[2], uA[2], uB[2];
    #pragma unroll
    for (int b_ = 0; b_ < 2; b_++) {
        sA[b_] = (uint32_t)__cvta_generic_to_shared(Asb[b_] + g_row * STR + g_k4);
        sB[b_] = (uint32_t)__cvta_generic_to_shared(Bsb[b_] + g_row * STR + g_k4);
        uA[b_] = (uint32_t)__cvta_generic_to_shared(Asb[b_]);
        uB[b_] = (uint32_t)__cvta_generic_to_shared(Bsb[b_]);
    }

    const int ntiles = Kx / BK;

    auto issue = [&](int kt, int buf) {
        const float* Ag = Aptr + kt * BK;
        const float* Bg = Bptr + kt * BK;
        #pragma unroll
        for (int t = 0; t < 4; t++) {
            cp_async16(sA[buf] + t * (32 * STR * 4), Ag + (size_t)(t * 32) * Kx);
            cp_async16(sB[buf] + t * (32 * STR * 4), Bg + (size_t)(t * 32) * Kx);
        }
        cp_commit();
    };

    float acc[4][4][4];
    #pragma unroll
    for (int i = 0; i < 4; i++)
        #pragma unroll
        for (int j = 0; j < 4; j++)
            #pragma unroll
            for (int c = 0; c < 4; c++) acc[i][j][c] = 0.f;

    issue(0, 0);

    for (int kt = 0; kt < ntiles; kt++) {
        cp_wait0();
        __syncthreads();
        if (kt + 1 < ntiles) issue(kt + 1, (kt + 1) & 1);

        const int buf = kt & 1;
        const uint32_t uAb = uA[buf];
        const uint32_t uBb = uB[buf];
        #pragma unroll
        for (int s = 0; s < 4; s++) {
            const int k0 = s * 8;
            uint32_t afr[4][4];
            #pragma unroll
            for (int mt = 0; mt < 4; mt++)
                ldsm_x4(afr[mt], uAb + (uint32_t)(((wm * 64 + mt * 16 + a_lrow) * STR + k0 + a_lcol) * 4));
            #pragma unroll
            for (int p = 0; p < 2; p++) {
                uint32_t bfr[4];
                ldsm_x4(bfr, uBb + (uint32_t)(((wn * 32 + p * 16 + b_lrow) * STR + k0 + b_lcol) * 4));
                #pragma unroll
                for (int mt = 0; mt < 4; mt++) {
                    mma_tf32(acc[mt][2 * p    ], afr[mt], bfr[0], bfr[1]);
                    mma_tf32(acc[mt][2 * p + 1], afr[mt], bfr[2], bfr[3]);
                }
            }
        }
    }

    #pragma unroll
    for (int mt = 0; mt < 4; mt++) {
        #pragma unroll
        for (int nt = 0; nt < 4; nt++) {
            int row = bm + wm * 64 + mt * 16 + grp;
            int col = bn + wn * 32 + nt * 8 + qid * 2;
            float2 v0 = make_float2(acc[mt][nt][0], acc[mt][nt][1]);
            float2 v1 = make_float2(acc[mt][nt][2], acc[mt][nt][3]);
            if (HAS_BIAS) {
                float2 bb = *(const float2*)&bias[col];
                v0.x += bb.x; v0.y += bb.y;
                v1.x += bb.x; v1.y += bb.y;
            }
            if (ROUND_OUT) {
                v0.x = to_tf32(v0.x); v0.y = to_tf32(v0.y);
                v1.x = to_tf32(v1.x); v1.y = to_tf32(v1.y);
            }
            *(float2*)&Cmat[(size_t)row * Nx + col]       = v0;
            *(float2*)&Cmat[(size_t)(row + 8) * Nx + col] = v1;
        }
    }
}

// ---------------------------------------------------------------------------
// MMA flash-attention (tf32, causal), 128-query tiles, 8 warps,
// K-tiles of 32, cp.async double-buffered K/V.
// Q-fragments hoisted into registers. V-fragments for the PV stage are
// PRELOADED into registers right after the S MMAs (they depend only on the
// arrived K/V buffer), letting the 64 scalar-LDS latencies overlap the
// softmax dependency chain. No minBlocks cap: registers float (~190),
// 1 CTA/SM (R12 showed occupancy-insensitivity).
// ---------------------------------------------------------------------------
__global__ __launch_bounds__(256)
void attn_mma_kernel(const float* __restrict__ qkv, float* __restrict__ y)
{
    constexpr int STR  = 68;   // Q/K/V row stride (64 + 4 pad)
    constexpr int PSTR = 36;   // P row stride (32 + 4 pad)
    constexpr int KT   = 32;   // K-tile rows
    extern __shared__ float sm[];
    float* Qs  = sm;                     // [128 q][68]
    float* Ksb = Qs  + 128 * STR;        // [2][32 j][68]
    float* Vsb = Ksb + 2 * KT * STR;     // [2][32 j][68]
    float* Ps  = Vsb + 2 * KT * STR;     // [8 warps][16 r][36]

    const int tid  = threadIdx.x;
    const int lane = tid & 31;
    const int w    = tid >> 5;
    const int grp  = lane >> 2;
    const int qid  = lane & 3;
    const int qt   = (int)gridDim.x - 1 - (int)blockIdx.x;  // longest first
    const int bh   = blockIdx.y;
    const int b    = bh >> 4;
    const int h    = bh & 15;
    const float scale = 0.125f;

    const int a_lrow = ((lane >> 3) & 1) * 8 + (lane & 7);
    const int a_lcol = (lane >> 4) * 4;
    const int b_lrow = (lane >> 4) * 8 + (lane & 7);
    const int b_lcol = ((lane >> 3) & 1) * 4;

    const float* qbase = qkv + (size_t)(b * SEQ) * (3 * CH) + h * HD;
    const float* kbase = qbase + CH;
    const float* vbase = qbase + 2 * CH;

    float* Pw = Ps + w * 16 * PSTR;
    const uint32_t uQ  = (uint32_t)__cvta_generic_to_shared(Qs);
    const uint32_t uKs = (uint32_t)__cvta_generic_to_shared(Ksb);
    const uint32_t uP  = (uint32_t)__cvta_generic_to_shared(Pw);

    // Load Q tile 128x64 into smem (scale exact), then hoist this warp's
    // A-fragments for all 8 k-steps into registers.
    #pragma unroll
    for (int t = 0; t < 8; t++) {
        int f   = tid + t * 256;
        int row = f >> 4;
        int c4  = (f & 15) * 4;
        float4 v = *(const float4*)&qbase[(size_t)(qt * 128 + row) * (3 * CH) + c4];
        v.x *= scale; v.y *= scale; v.z *= scale; v.w *= scale;
        *(float4*)&Qs[row * STR + c4] = v;
    }
    __syncthreads();
    uint32_t qfr[8][4];
    #pragma unroll
    for (int s = 0; s < 8; s++)
        ldsm_x4(qfr[s], uQ + (uint32_t)(((16 * w + a_lrow) * STR + s * 8 + a_lcol) * 4));

    // cp.async K/V tile issue: 32 rows x 64 floats each
    const int ld_row = tid >> 4;
    const int ld_c4  = (tid & 15) * 4;
    const uint32_t uVs = (uint32_t)__cvta_generic_to_shared(Vsb);
    auto issueKV = [&](int kt, int buf) {
        const float* Kg = kbase + (size_t)(kt * KT + ld_row) * (3 * CH) + ld_c4;
        const float* Vg = vbase + (size_t)(kt * KT + ld_row) * (3 * CH) + ld_c4;
        uint32_t dK = uKs + (uint32_t)((buf * KT + ld_row) * STR + ld_c4) * 4;
        uint32_t dV = uVs + (uint32_t)((buf * KT + ld_row) * STR + ld_c4) * 4;
        cp_async16(dK,                Kg);
        cp_async16(dK + 16 * STR * 4, Kg + (size_t)16 * (3 * CH));
        cp_async16(dV,                Vg);
        cp_async16(dV + 16 * STR * 4, Vg + (size_t)16 * (3 * CH));
        cp_commit();
    };

    float o[8][4];
    #pragma unroll
    for (int nt = 0; nt < 8; nt++)
        #pragma unroll
        for (int c = 0; c < 4; c++) o[nt][c] = 0.f;
    float m0 = -1e30f, m1 = -1e30f, l0 = 0.f, l1 = 0.f;

    const int row0 = 16 * w + grp;
    const int gi0  = qt * 128 + row0;
    const int gi1  = gi0 + 8;

    const int last = 4 * qt + 3;
    issueKV(0, 0);

    for (int kt = 0; kt <= last; kt++) {
        cp_wait0();
        __syncthreads();
        if (kt < last) issueKV(kt + 1, (kt + 1) & 1);

        const int buf = kt & 1;
        const uint32_t uKb = uKs + (uint32_t)(buf * KT * STR) * 4;
        const float*   Vb  = Vsb + buf * KT * STR;

        // ---- S = Q @ K^T : Q-frags from registers; 2 K-LDSM per k8 step
        float sfr[4][4];
        #pragma unroll
        for (int nt = 0; nt < 4; nt++)
            #pragma unroll
            for (int c = 0; c < 4; c++) sfr[nt][c] = 0.f;

        #pragma unroll
        for (int s = 0; s < 8; s++) {
            const int k0 = s * 8;
            #pragma unroll
            for (int p = 0; p < 2; p++) {
                uint32_t kf[4];
                ldsm_x4(kf, uKb + (uint32_t)(((p * 16 + b_lrow) * STR + k0 + b_lcol) * 4));
                mma_tf32(sfr[2 * p    ], qfr[s], kf[0], kf[1]);
                mma_tf32(sfr[2 * p + 1], qfr[s], kf[2], kf[3]);
            }
        }

        // ---- PRELOAD V fragments for PV (independent of softmax; the
        //      64 LDS latencies overlap the softmax chain below)
        uint32_t vf0[4][8], vf1[4][8];
        #pragma unroll
        for (int s = 0; s < 4; s++) {
            const float* v0r = Vb + (s * 8 + qid    ) * STR + grp;
            const float* v1r = Vb + (s * 8 + qid + 4) * STR + grp;
            #pragma unroll
            for (int nt = 0; nt < 8; nt++) {
                vf0[s][nt] = __float_as_uint(v0r[nt * 8]);
                vf1[s][nt] = __float_as_uint(v1r[nt * 8]);
            }
        }

        // ---- causal mask
        if (kt >= 4 * qt) {
            #pragma unroll
            for (int nt = 0; nt < 4; nt++) {
                int j0 = kt * KT + nt * 8 + qid * 2;
                if (j0     > gi0) sfr[nt][0] = -1e30f;
                if (j0 + 1 > gi0) sfr[nt][1] = -1e30f;
                if (j0     > gi1) sfr[nt][2] = -1e30f;
                if (j0 + 1 > gi1) sfr[nt][3] = -1e30f;
            }
        }

        // ---- online softmax
        float mx0 = -1e30f, mx1 = -1e30f;
        #pragma unroll
        for (int nt = 0; nt < 4; nt++) {
            mx0 = fmaxf(mx0, fmaxf(sfr[nt][0], sfr[nt][1]));
            mx1 = fmaxf(mx1, fmaxf(sfr[nt][2], sfr[nt][3]));
        }
        #pragma unroll
        for (int off = 1; off <= 2; off <<= 1) {
            mx0 = fmaxf(mx0, __shfl_xor_sync(0xffffffffu, mx0, off));
            mx1 = fmaxf(mx1, __shfl_xor_sync(0xffffffffu, mx1, off));
        }
        float mnew0 = fmaxf(m0, mx0), mnew1 = fmaxf(m1, mx1);
        float alpha0 = __expf(m0 - mnew0), alpha1 = __expf(m1 - mnew1);
        float sum0 = 0.f, sum1 = 0.f;
        #pragma unroll
        for (int nt = 0; nt < 4; nt++) {
            sfr[nt][0] = __expf(sfr[nt][0] - mnew0);
            sfr[nt][1] = __expf(sfr[nt][1] - mnew0);
            sfr[nt][2] = __expf(sfr[nt][2] - mnew1);
            sfr[nt][3] = __expf(sfr[nt][3] - mnew1);
            sum0 += sfr[nt][0] + sfr[nt][1];
            sum1 += sfr[nt][2] + sfr[nt][3];
        }
        #pragma unroll
        for (int off = 1; off <= 2; off <<= 1) {
            sum0 += __shfl_xor_sync(0xffffffffu, sum0, off);
            sum1 += __shfl_xor_sync(0xffffffffu, sum1, off);
        }
        l0 = l0 * alpha0 + sum0;  m0 = mnew0;
        l1 = l1 * alpha1 + sum1;  m1 = mnew1;

        // ---- write P (tf32) to per-warp smem; rescale O
        #pragma unroll
        for (int nt = 0; nt < 4; nt++) {
            int cc = nt * 8 + qid * 2;
            float2 p0 = make_float2(to_tf32(sfr[nt][0]), to_tf32(sfr[nt][1]));
            float2 p1 = make_float2(to_tf32(sfr[nt][2]), to_tf32(sfr[nt][3]));
            *(float2*)&Pw[(grp    ) * PSTR + cc] = p0;
            *(float2*)&Pw[(grp + 8) * PSTR + cc] = p1;
        }
        #pragma unroll
        for (int nt = 0; nt < 8; nt++) {
            o[nt][0] *= alpha0; o[nt][1] *= alpha0;
            o[nt][2] *= alpha1; o[nt][3] *= alpha1;
        }
        __syncwarp();

        // ---- O += P @ V : 4 k8-steps, V-frags already in registers
        #pragma unroll
        for (int s = 0; s < 4; s++) {
            const int k0 = s * 8;
            uint32_t pf[4];
            ldsm_x4(pf, uP + (uint32_t)((a_lrow * PSTR + k0 + a_lcol) * 4));
            #pragma unroll
            for (int nt = 0; nt < 8; nt++)
                mma_tf32(o[nt], pf, vf0[s][nt], vf1[s][nt]);
        }
        __syncwarp();
    }

    // ---- normalize + write y (tf32-rounded, feeds tf32 GEMM2)
    float inv0 = 1.0f / l0, inv1 = 1.0f / l1;
    #pragma unroll
    for (int nt = 0; nt < 8; nt++) {
        int d = nt * 8 + qid * 2;
        float2 v0 = make_float2(to_tf32(o[nt][0] * inv0), to_tf32(o[nt][1] * inv0));
        float2 v1 = make_float2(to_tf32(o[nt][2] * inv1), to_tf32(o[nt][3] * inv1));
        *(float2*)&y[(size_t)(b * SEQ + gi0) * CH + h * HD + d] = v0;
        *(float2*)&y[(size_t)(b * SEQ + gi1) * CH + h * HD + d] = v1;
    }
}

// ---------------------------------------------------------------------------

static constexpr int GEMM_SMEM = (4 * 128 * 36) * 4;                              // 73728 B
static constexpr int ATTN_SMEM = (128 * 68 + 2 * 32 * 68 * 2 + 8 * 16 * 36) * 4;  // 88064 B

extern "C" void kernel_launch(void* const* d_in, const int* in_sizes, int n_in,
                              void* d_out, int out_size)
{
    (void)in_sizes; (void)n_in; (void)out_size;
    const float* x     = (const float*)d_in[0];
    const float* w_qkv = (const float*)d_in[1];
    const float* w_out = (const float*)d_in[2];
    const float* b_out = (const float*)d_in[3];
    float* out = (float*)d_out;

    float *qkv, *y, *xc, *wqT, *woT;
    cudaGetSymbolAddress((void**)&qkv, g_qkv);
    cudaGetSymbolAddress((void**)&y,   g_y);
    cudaGetSymbolAddress((void**)&xc,  g_x);
    cudaGetSymbolAddress((void**)&wqT, g_wqT);
    cudaGetSymbolAddress((void**)&woT, g_woT);

    cudaFuncSetAttribute(gemm_tf32_kernel<false, true>,
                         cudaFuncAttributeMaxDynamicSharedMemorySize, GEMM_SMEM);
    cudaFuncSetAttribute(gemm_tf32_kernel<true, false>,
                         cudaFuncAttributeMaxDynamicSharedMemorySize, GEMM_SMEM);
    cudaFuncSetAttribute(attn_mma_kernel,
                         cudaFuncAttributeMaxDynamicSharedMemorySize, ATTN_SMEM);

    // 0) operand prep: tf32-round x; transpose + tf32-round weights to [N][K]
    cvt_tf32_kernel<<<(MROWS * CH / 4 + 255) / 256, 256>>>(
        (const float4*)x, (float4*)xc, MROWS * CH / 4);
    transpose_tf32_kernel<<<dim3(3 * CH / 32, CH / 32), dim3(32, 8)>>>(
        w_qkv, wqT, CH, 3 * CH);
    transpose_tf32_kernel<<<dim3(CH / 32, CH / 32), dim3(32, 8)>>>(
        w_out, woT, CH, CH);

    // 1) qkv = x @ w_qkv  (tf32 TC, all-LDSM), output tf32-rounded
    gemm_tf32_kernel<false, true><<<dim3(3 * CH / 128, MROWS / 128), 256, GEMM_SMEM>>>(
        xc, wqT, nullptr, qkv, MROWS, 3 * CH, CH);

    // 2) causal flash attention -> y (tf32 TC, V-frags preloaded into regs)
    attn_mma_kernel<<<dim3(SEQ / 128, BATCH * NH), 256, ATTN_SMEM>>>(qkv, y);

    // 3) out = y @ w_out + b_out  (tf32 TC, all-LDSM), fp32 output
    gemm_tf32_kernel<true, false><<<dim3(CH / 128, MROWS / 128), 256, GEMM_SMEM>>>(
        y, woT, b_out, out, MROWS, CH, CH);
}

// round 15
// speedup vs baseline: 1.0862x; 1.0862x over previous
#include <cuda_runtime.h>
#include <cstdint>

#define BATCH 2
#define SEQ   2048
#define CH    1024
#define NH    16
#define HD    64
#define MROWS (BATCH*SEQ)   /* 4096 */

// Scratch (allocation-free rule: __device__ globals)
__device__ float g_qkv[MROWS * 3 * CH];   // tf32-rounded qkv
__device__ float g_y  [MROWS * CH];       // tf32-rounded attn out
__device__ float g_x  [MROWS * CH];       // tf32-rounded x
__device__ float g_wqT[3 * CH * CH];      // transposed + tf32 w_qkv  [3C][C]
__device__ float g_woT[CH * CH];          // transposed + tf32 w_out  [C][C]

// ---------------------------------------------------------------------------
// TF32 / MMA / cp.async / ldmatrix helpers
// ---------------------------------------------------------------------------
__device__ __forceinline__ uint32_t to_tf32_bits(float x) {
    uint32_t y;
    asm("cvt.rna.tf32.f32 %0, %1;" : "=r"(y) : "f"(x));
    return y;
}
__device__ __forceinline__ float to_tf32(float x) {
    return __uint_as_float(to_tf32_bits(x));
}
__device__ __forceinline__ float exp2_approx(float x) {
    float y;
    asm("ex2.approx.f32 %0, %1;" : "=f"(y) : "f"(x));
    return y;
}

__device__ __forceinline__ void mma_tf32(float c[4], const uint32_t a[4], const uint32_t b0, const uint32_t b1) {
    asm volatile(
        "mma.sync.aligned.m16n8k8.row.col.f32.tf32.tf32.f32 "
        "{%0,%1,%2,%3}, {%4,%5,%6,%7}, {%8,%9}, {%0,%1,%2,%3};"
        : "+f"(c[0]), "+f"(c[1]), "+f"(c[2]), "+f"(c[3])
        : "r"(a[0]), "r"(a[1]), "r"(a[2]), "r"(a[3]),
          "r"(b0), "r"(b1));
}

__device__ __forceinline__ void ldsm_x4(uint32_t r[4], uint32_t saddr) {
    asm volatile("ldmatrix.sync.aligned.m8n8.x4.shared.b16 {%0,%1,%2,%3}, [%4];"
        : "=r"(r[0]), "=r"(r[1]), "=r"(r[2]), "=r"(r[3]) : "r"(saddr));
}

__device__ __forceinline__ void cp_async16(uint32_t saddr, const void* gptr) {
    asm volatile("cp.async.cg.shared.global [%0], [%1], 16;" :: "r"(saddr), "l"(gptr));
}
__device__ __forceinline__ void cp_commit() { asm volatile("cp.async.commit_group;"); }
__device__ __forceinline__ void cp_wait0()  { asm volatile("cp.async.wait_group 0;"); }

// ---------------------------------------------------------------------------
// Elementwise tf32 rounding (float4 granularity)
// ---------------------------------------------------------------------------
__global__ void cvt_tf32_kernel(const float4* __restrict__ in, float4* __restrict__ out, int n4)
{
    int i = blockIdx.x * blockDim.x + threadIdx.x;
    if (i < n4) {
        float4 v = in[i];
        v.x = to_tf32(v.x); v.y = to_tf32(v.y);
        v.z = to_tf32(v.z); v.w = to_tf32(v.w);
        out[i] = v;
    }
}

// Transpose + tf32 round: in [R][Cc] -> out [Cc][R]
__global__ void transpose_tf32_kernel(const float* __restrict__ in, float* __restrict__ out,
                                      int R, int Cc)
{
    __shared__ float tile[32][33];
    int bx = blockIdx.x * 32;   // Cc base
    int by = blockIdx.y * 32;   // R base
    int tx = threadIdx.x, ty = threadIdx.y;
    #pragma unroll
    for (int i = 0; i < 32; i += 8)
        tile[ty + i][tx] = in[(size_t)(by + ty + i) * Cc + bx + tx];
    __syncthreads();
    #pragma unroll
    for (int i = 0; i < 32; i += 8)
        out[(size_t)(bx + ty + i) * R + by + tx] = to_tf32(tile[tx][ty + i]);
}

// ---------------------------------------------------------------------------
// TF32 tensor-core GEMM, cp.async double-buffered, BOTH operand fragments
// via ldmatrix. C = A(MxK) @ Bt^T (+bias); A [M][K], Bt [N][K].
// (identical to R13 passing kernel)
// ---------------------------------------------------------------------------
template<bool HAS_BIAS, bool ROUND_OUT>
__global__ __launch_bounds__(256, 2)
void gemm_tf32_kernel(const float* __restrict__ A, const float* __restrict__ Bt,
                      const float* __restrict__ bias, float* __restrict__ Cmat,
                      int Mx, int Nx, int Kx)
{
    constexpr int BM = 128, BK = 32;
    constexpr int STR = 36;
    constexpr int TSZ = BM * STR;            // floats per tile buffer
    extern __shared__ float smem[];
    float* Asb[2] = { smem,           smem + TSZ };
    float* Bsb[2] = { smem + 2 * TSZ, smem + 3 * TSZ };

    const int tid  = threadIdx.x;
    const int lane = tid & 31;
    const int wid  = tid >> 5;
    const int wm   = wid >> 2;
    const int wn   = wid & 3;
    const int grp  = lane >> 2;
    const int qid  = lane & 3;
    const int bm = blockIdx.y * BM;
    const int bn = blockIdx.x * BM;

    const int a_lrow = ((lane >> 3) & 1) * 8 + (lane & 7);   // A-pattern row
    const int a_lcol = (lane >> 4) * 4;
    const int b_lrow = (lane >> 4) * 8 + (lane & 7);         // B-pattern row
    const int b_lcol = ((lane >> 3) & 1) * 4;

    const int g_row = tid >> 3, g_k4 = (tid & 7) * 4;        // cp.async coords

    const float* Aptr = A  + (size_t)(bm + g_row) * Kx + g_k4;
    const float* Bptr = Bt + (size_t)(bn + g_row) * Kx + g_k4;

    uint32_t sA[2], sB[2], uA[2], uB[2];
    #pragma unroll
    for (int b_ = 0; b_ < 2; b_++) {
        sA[b_] = (uint32_t)__cvta_generic_to_shared(Asb[b_] + g_row * STR + g_k4);
        sB[b_] = (uint32_t)__cvta_generic_to_shared(Bsb[b_] + g_row * STR + g_k4);
        uA[b_] = (uint32_t)__cvta_generic_to_shared(Asb[b_]);
        uB[b_] = (uint32_t)__cvta_generic_to_shared(Bsb[b_]);
    }

    const int ntiles = Kx / BK;

    auto issue = [&](int kt, int buf) {
        const float* Ag = Aptr + kt * BK;
        const float* Bg = Bptr + kt * BK;
        #pragma unroll
        for (int t = 0; t < 4; t++) {
            cp_async16(sA[buf] + t * (32 * STR * 4), Ag + (size_t)(t * 32) * Kx);
            cp_async16(sB[buf] + t * (32 * STR * 4), Bg + (size_t)(t * 32) * Kx);
        }
        cp_commit();
    };

    float acc[4][4][4];
    #pragma unroll
    for (int i = 0; i < 4; i++)
        #pragma unroll
        for (int j = 0; j < 4; j++)
            #pragma unroll
            for (int c = 0; c < 4; c++) acc[i][j][c] = 0.f;

    issue(0, 0);

    for (int kt = 0; kt < ntiles; kt++) {
        cp_wait0();
        __syncthreads();
        if (kt + 1 < ntiles) issue(kt + 1, (kt + 1) & 1);

        const int buf = kt & 1;
        const uint32_t uAb = uA[buf];
        const uint32_t uBb = uB[buf];
        #pragma unroll
        for (int s = 0; s < 4; s++) {
            const int k0 = s * 8;
            uint32_t afr[4][4];
            #pragma unroll
            for (int mt = 0; mt < 4; mt++)
                ldsm_x4(afr[mt], uAb + (uint32_t)(((wm * 64 + mt * 16 + a_lrow) * STR + k0 + a_lcol) * 4));
            #pragma unroll
            for (int p = 0; p < 2; p++) {
                uint32_t bfr[4];
                ldsm_x4(bfr, uBb + (uint32_t)(((wn * 32 + p * 16 + b_lrow) * STR + k0 + b_lcol) * 4));
                #pragma unroll
                for (int mt = 0; mt < 4; mt++) {
                    mma_tf32(acc[mt][2 * p    ], afr[mt], bfr[0], bfr[1]);
                    mma_tf32(acc[mt][2 * p + 1], afr[mt], bfr[2], bfr[3]);
                }
            }
        }
    }

    #pragma unroll
    for (int mt = 0; mt < 4; mt++) {
        #pragma unroll
        for (int nt = 0; nt < 4; nt++) {
            int row = bm + wm * 64 + mt * 16 + grp;
            int col = bn + wn * 32 + nt * 8 + qid * 2;
            float2 v0 = make_float2(acc[mt][nt][0], acc[mt][nt][1]);
            float2 v1 = make_float2(acc[mt][nt][2], acc[mt][nt][3]);
            if (HAS_BIAS) {
                float2 bb = *(const float2*)&bias[col];
                v0.x += bb.x; v0.y += bb.y;
                v1.x += bb.x; v1.y += bb.y;
            }
            if (ROUND_OUT) {
                v0.x = to_tf32(v0.x); v0.y = to_tf32(v0.y);
                v1.x = to_tf32(v1.x); v1.y = to_tf32(v1.y);
            }
            *(float2*)&Cmat[(size_t)row * Nx + col]       = v0;
            *(float2*)&Cmat[(size_t)(row + 8) * Nx + col] = v1;
        }
    }
}

// ---------------------------------------------------------------------------
// MMA flash-attention (tf32, causal), 128-query tiles, 8 warps,
// K-tiles of 32, cp.async double-buffered K/V, 2 CTAs/SM.
// EXACT R13 structure (the 502.6us config), with ONE change: log2(e) folded
// into the Q pre-scale so softmax uses raw ex2.approx (no per-element FMUL).
// ---------------------------------------------------------------------------
__global__ __launch_bounds__(256, 2)
void attn_mma_kernel(const float* __restrict__ qkv, float* __restrict__ y)
{
    constexpr int STR  = 68;   // Q/K/V row stride (64 + 4 pad)
    constexpr int PSTR = 36;   // P row stride (32 + 4 pad)
    constexpr int KT   = 32;   // K-tile rows
    extern __shared__ float sm[];
    float* Qs  = sm;                     // [128 q][68]
    float* Ksb = Qs  + 128 * STR;        // [2][32 j][68]
    float* Vsb = Ksb + 2 * KT * STR;     // [2][32 j][68]
    float* Ps  = Vsb + 2 * KT * STR;     // [8 warps][16 r][36]

    const int tid  = threadIdx.x;
    const int lane = tid & 31;
    const int w    = tid >> 5;
    const int grp  = lane >> 2;
    const int qid  = lane & 3;
    const int qt   = (int)gridDim.x - 1 - (int)blockIdx.x;  // longest first
    const int bh   = blockIdx.y;
    const int b    = bh >> 4;
    const int h    = bh & 15;
    // 1/sqrt(64) * log2(e): softmax then uses ex2 directly
    const float qscale = 0.125f * 1.44269504088896340736f;

    const int a_lrow = ((lane >> 3) & 1) * 8 + (lane & 7);
    const int a_lcol = (lane >> 4) * 4;
    const int b_lrow = (lane >> 4) * 8 + (lane & 7);
    const int b_lcol = ((lane >> 3) & 1) * 4;

    const float* qbase = qkv + (size_t)(b * SEQ) * (3 * CH) + h * HD;
    const float* kbase = qbase + CH;
    const float* vbase = qbase + 2 * CH;

    float* Pw = Ps + w * 16 * PSTR;
    const uint32_t uQ  = (uint32_t)__cvta_generic_to_shared(Qs);
    const uint32_t uKs = (uint32_t)__cvta_generic_to_shared(Ksb);
    const uint32_t uP  = (uint32_t)__cvta_generic_to_shared(Pw);

    // Load Q tile 128x64 into smem (pre-scaled by qscale), then hoist this
    // warp's A-fragments for all 8 k-steps into registers.
    #pragma unroll
    for (int t = 0; t < 8; t++) {
        int f   = tid + t * 256;
        int row = f >> 4;
        int c4  = (f & 15) * 4;
        float4 v = *(const float4*)&qbase[(size_t)(qt * 128 + row) * (3 * CH) + c4];
        v.x *= qscale; v.y *= qscale; v.z *= qscale; v.w *= qscale;
        *(float4*)&Qs[row * STR + c4] = v;
    }
    __syncthreads();
    uint32_t qfr[8][4];
    #pragma unroll
    for (int s = 0; s < 8; s++)
        ldsm_x4(qfr[s], uQ + (uint32_t)(((16 * w + a_lrow) * STR + s * 8 + a_lcol) * 4));

    // cp.async K/V tile issue: 32 rows x 64 floats each
    const int ld_row = tid >> 4;
    const int ld_c4  = (tid & 15) * 4;
    const uint32_t uVs = (uint32_t)__cvta_generic_to_shared(Vsb);
    auto issueKV = [&](int kt, int buf) {
        const float* Kg = kbase + (size_t)(kt * KT + ld_row) * (3 * CH) + ld_c4;
        const float* Vg = vbase + (size_t)(kt * KT + ld_row) * (3 * CH) + ld_c4;
        uint32_t dK = uKs + (uint32_t)((buf * KT + ld_row) * STR + ld_c4) * 4;
        uint32_t dV = uVs + (uint32_t)((buf * KT + ld_row) * STR + ld_c4) * 4;
        cp_async16(dK,                Kg);
        cp_async16(dK + 16 * STR * 4, Kg + (size_t)16 * (3 * CH));
        cp_async16(dV,                Vg);
        cp_async16(dV + 16 * STR * 4, Vg + (size_t)16 * (3 * CH));
        cp_commit();
    };

    float o[8][4];
    #pragma unroll
    for (int nt = 0; nt < 8; nt++)
        #pragma unroll
        for (int c = 0; c < 4; c++) o[nt][c] = 0.f;
    float m0 = -1e30f, m1 = -1e30f, l0 = 0.f, l1 = 0.f;

    const int row0 = 16 * w + grp;
    const int gi0  = qt * 128 + row0;
    const int gi1  = gi0 + 8;

    const int last = 4 * qt + 3;
    issueKV(0, 0);

    for (int kt = 0; kt <= last; kt++) {
        cp_wait0();
        __syncthreads();
        if (kt < last) issueKV(kt + 1, (kt + 1) & 1);

        const int buf = kt & 1;
        const uint32_t uKb = uKs + (uint32_t)(buf * KT * STR) * 4;
        const float*   Vb  = Vsb + buf * KT * STR;

        // ---- S = Q @ K^T (log2-domain) : Q-frags from registers
        float sfr[4][4];
        #pragma unroll
        for (int nt = 0; nt < 4; nt++)
            #pragma unroll
            for (int c = 0; c < 4; c++) sfr[nt][c] = 0.f;

        #pragma unroll
        for (int s = 0; s < 8; s++) {
            const int k0 = s * 8;
            #pragma unroll
            for (int p = 0; p < 2; p++) {
                uint32_t kf[4];
                ldsm_x4(kf, uKb + (uint32_t)(((p * 16 + b_lrow) * STR + k0 + b_lcol) * 4));
                mma_tf32(sfr[2 * p    ], qfr[s], kf[0], kf[1]);
                mma_tf32(sfr[2 * p + 1], qfr[s], kf[2], kf[3]);
            }
        }

        // ---- causal mask
        if (kt >= 4 * qt) {
            #pragma unroll
            for (int nt = 0; nt < 4; nt++) {
                int j0 = kt * KT + nt * 8 + qid * 2;
                if (j0     > gi0) sfr[nt][0] = -1e30f;
                if (j0 + 1 > gi0) sfr[nt][1] = -1e30f;
                if (j0     > gi1) sfr[nt][2] = -1e30f;
                if (j0 + 1 > gi1) sfr[nt][3] = -1e30f;
            }
        }

        // ---- online softmax (base-2: ex2.approx, no log2e FMULs)
        float mx0 = -1e30f, mx1 = -1e30f;
        #pragma unroll
        for (int nt = 0; nt < 4; nt++) {
            mx0 = fmaxf(mx0, fmaxf(sfr[nt][0], sfr[nt][1]));
            mx1 = fmaxf(mx1, fmaxf(sfr[nt][2], sfr[nt][3]));
        }
        #pragma unroll
        for (int off = 1; off <= 2; off <<= 1) {
            mx0 = fmaxf(mx0, __shfl_xor_sync(0xffffffffu, mx0, off));
            mx1 = fmaxf(mx1, __shfl_xor_sync(0xffffffffu, mx1, off));
        }
        float mnew0 = fmaxf(m0, mx0), mnew1 = fmaxf(m1, mx1);
        float alpha0 = exp2_approx(m0 - mnew0), alpha1 = exp2_approx(m1 - mnew1);
        float sum0 = 0.f, sum1 = 0.f;
        #pragma unroll
        for (int nt = 0; nt < 4; nt++) {
            sfr[nt][0] = exp2_approx(sfr[nt][0] - mnew0);
            sfr[nt][1] = exp2_approx(sfr[nt][1] - mnew0);
            sfr[nt][2] = exp2_approx(sfr[nt][2] - mnew1);
            sfr[nt][3] = exp2_approx(sfr[nt][3] - mnew1);
            sum0 += sfr[nt][0] + sfr[nt][1];
            sum1 += sfr[nt][2] + sfr[nt][3];
        }
        #pragma unroll
        for (int off = 1; off <= 2; off <<= 1) {
            sum0 += __shfl_xor_sync(0xffffffffu, sum0, off);
            sum1 += __shfl_xor_sync(0xffffffffu, sum1, off);
        }
        l0 = l0 * alpha0 + sum0;  m0 = mnew0;
        l1 = l1 * alpha1 + sum1;  m1 = mnew1;

        // ---- write P (tf32) to per-warp smem; rescale O
        #pragma unroll
        for (int nt = 0; nt < 4; nt++) {
            int cc = nt * 8 + qid * 2;
            float2 p0 = make_float2(to_tf32(sfr[nt][0]), to_tf32(sfr[nt][1]));
            float2 p1 = make_float2(to_tf32(sfr[nt][2]), to_tf32(sfr[nt][3]));
            *(float2*)&Pw[(grp    ) * PSTR + cc] = p0;
            *(float2*)&Pw[(grp + 8) * PSTR + cc] = p1;
        }
        #pragma unroll
        for (int nt = 0; nt < 8; nt++) {
            o[nt][0] *= alpha0; o[nt][1] *= alpha0;
            o[nt][2] *= alpha1; o[nt][3] *= alpha1;
        }
        __syncwarp();

        // ---- O += P @ V : 4 k8-steps (j = 32)
        #pragma unroll
        for (int s = 0; s < 4; s++) {
            const int k0 = s * 8;
            uint32_t pf[4];
            ldsm_x4(pf, uP + (uint32_t)((a_lrow * PSTR + k0 + a_lcol) * 4));
            const float* v0r = Vb + (k0 + qid    ) * STR + grp;
            const float* v1r = Vb + (k0 + qid + 4) * STR + grp;
            #pragma unroll
            for (int nt = 0; nt < 8; nt++) {
                uint32_t bf0 = __float_as_uint(v0r[nt * 8]);
                uint32_t bf1 = __float_as_uint(v1r[nt * 8]);
                mma_tf32(o[nt], pf, bf0, bf1);
            }
        }
        __syncwarp();
    }

    // ---- normalize + write y (tf32-rounded, feeds tf32 GEMM2)
    float inv0 = 1.0f / l0, inv1 = 1.0f / l1;
    #pragma unroll
    for (int nt = 0; nt < 8; nt++) {
        int d = nt * 8 + qid * 2;
        float2 v0 = make_float2(to_tf32(o[nt][0] * inv0), to_tf32(o[nt][1] * inv0));
        float2 v1 = make_float2(to_tf32(o[nt][2] * inv1), to_tf32(o[nt][3] * inv1));
        *(float2*)&y[(size_t)(b * SEQ + gi0) * CH + h * HD + d] = v0;
        *(float2*)&y[(size_t)(b * SEQ + gi1) * CH + h * HD + d] = v1;
    }
}

// ---------------------------------------------------------------------------

static constexpr int GEMM_SMEM = (4 * 128 * 36) * 4;                              // 73728 B
static constexpr int ATTN_SMEM = (128 * 68 + 2 * 32 * 68 * 2 + 8 * 16 * 36) * 4;  // 88064 B

extern "C" void kernel_launch(void* const* d_in, const int* in_sizes, int n_in,
                              void* d_out, int out_size)
{
    (void)in_sizes; (void)n_in; (void)out_size;
    const float* x     = (const float*)d_in[0];
    const float* w_qkv = (const float*)d_in[1];
    const float* w_out = (const float*)d_in[2];
    const float* b_out = (const float*)d_in[3];
    float* out = (float*)d_out;

    float *qkv, *y, *xc, *wqT, *woT;
    cudaGetSymbolAddress((void**)&qkv, g_qkv);
    cudaGetSymbolAddress((void**)&y,   g_y);
    cudaGetSymbolAddress((void**)&xc,  g_x);
    cudaGetSymbolAddress((void**)&wqT, g_wqT);
    cudaGetSymbolAddress((void**)&woT, g_woT);

    cudaFuncSetAttribute(gemm_tf32_kernel<false, true>,
                         cudaFuncAttributeMaxDynamicSharedMemorySize, GEMM_SMEM);
    cudaFuncSetAttribute(gemm_tf32_kernel<true, false>,
                         cudaFuncAttributeMaxDynamicSharedMemorySize, GEMM_SMEM);
    cudaFuncSetAttribute(attn_mma_kernel,
                         cudaFuncAttributeMaxDynamicSharedMemorySize, ATTN_SMEM);

    // 0) operand prep: tf32-round x; transpose + tf32-round weights to [N][K]
    cvt_tf32_kernel<<<(MROWS * CH / 4 + 255) / 256, 256>>>(
        (const float4*)x, (float4*)xc, MROWS * CH / 4);
    transpose_tf32_kernel<<<dim3(3 * CH / 32, CH / 32), dim3(32, 8)>>>(
        w_qkv, wqT, CH, 3 * CH);
    transpose_tf32_kernel<<<dim3(CH / 32, CH / 32), dim3(32, 8)>>>(
        w_out, woT, CH, CH);

    // 1) qkv = x @ w_qkv  (tf32 TC, all-LDSM), output tf32-rounded
    gemm_tf32_kernel<false, true><<<dim3(3 * CH / 128, MROWS / 128), 256, GEMM_SMEM>>>(
        xc, wqT, nullptr, qkv, MROWS, 3 * CH, CH);

    // 2) causal flash attention -> y (tf32 TC, R13 structure + ex2 softmax)
    attn_mma_kernel<<<dim3(SEQ / 128, BATCH * NH), 256, ATTN_SMEM>>>(qkv, y);

    // 3) out = y @ w_out + b_out  (tf32 TC, all-LDSM), fp32 output
    gemm_tf32_kernel<true, false><<<dim3(CH / 128, MROWS / 128), 256, GEMM_SMEM>>>(
        y, woT, b_out, out, MROWS, CH, CH);
}

// round 16
// speedup vs baseline: 1.1079x; 1.0200x over previous
#include <cuda_runtime.h>
#include <cstdint>

#define BATCH 2
#define SEQ   2048
#define CH    1024
#define NH    16
#define HD    64
#define MROWS (BATCH*SEQ)   /* 4096 */

// Scratch (allocation-free rule: __device__ globals)
__device__ float g_qkv[MROWS * 3 * CH];   // tf32-rounded qkv
__device__ float g_y  [MROWS * CH];       // tf32-rounded attn out
__device__ float g_x  [MROWS * CH];       // tf32-rounded x
__device__ float g_wqT[3 * CH * CH];      // transposed + tf32 w_qkv  [3C][C]
__device__ float g_woT[CH * CH];          // transposed + tf32 w_out  [C][C]

// ---------------------------------------------------------------------------
// TF32 / MMA / cp.async / ldmatrix helpers
// ---------------------------------------------------------------------------
__device__ __forceinline__ uint32_t to_tf32_bits(float x) {
    uint32_t y;
    asm("cvt.rna.tf32.f32 %0, %1;" : "=r"(y) : "f"(x));
    return y;
}
__device__ __forceinline__ float to_tf32(float x) {
    return __uint_as_float(to_tf32_bits(x));
}
__device__ __forceinline__ float exp2_approx(float x) {
    float y;
    asm("ex2.approx.f32 %0, %1;" : "=f"(y) : "f"(x));
    return y;
}

__device__ __forceinline__ void mma_tf32(float c[4], const uint32_t a[4], const uint32_t b0, const uint32_t b1) {
    asm volatile(
        "mma.sync.aligned.m16n8k8.row.col.f32.tf32.tf32.f32 "
        "{%0,%1,%2,%3}, {%4,%5,%6,%7}, {%8,%9}, {%0,%1,%2,%3};"
        : "+f"(c[0]), "+f"(c[1]), "+f"(c[2]), "+f"(c[3])
        : "r"(a[0]), "r"(a[1]), "r"(a[2]), "r"(a[3]),
          "r"(b0), "r"(b1));
}

__device__ __forceinline__ void ldsm_x4(uint32_t r[4], uint32_t saddr) {
    asm volatile("ldmatrix.sync.aligned.m8n8.x4.shared.b16 {%0,%1,%2,%3}, [%4];"
        : "=r"(r[0]), "=r"(r[1]), "=r"(r[2]), "=r"(r[3]) : "r"(saddr));
}

__device__ __forceinline__ void cp_async16(uint32_t saddr, const void* gptr) {
    asm volatile("cp.async.cg.shared.global [%0], [%1], 16;" :: "r"(saddr), "l"(gptr));
}
__device__ __forceinline__ void cp_commit() { asm volatile("cp.async.commit_group;"); }
__device__ __forceinline__ void cp_wait0()  { asm volatile("cp.async.wait_group 0;"); }

// ---------------------------------------------------------------------------
// Elementwise tf32 rounding (float4 granularity)
// ---------------------------------------------------------------------------
__global__ void cvt_tf32_kernel(const float4* __restrict__ in, float4* __restrict__ out, int n4)
{
    int i = blockIdx.x * blockDim.x + threadIdx.x;
    if (i < n4) {
        float4 v = in[i];
        v.x = to_tf32(v.x); v.y = to_tf32(v.y);
        v.z = to_tf32(v.z); v.w = to_tf32(v.w);
        out[i] = v;
    }
}

// Transpose + tf32 round: in [R][Cc] -> out [Cc][R]
__global__ void transpose_tf32_kernel(const float* __restrict__ in, float* __restrict__ out,
                                      int R, int Cc)
{
    __shared__ float tile[32][33];
    int bx = blockIdx.x * 32;   // Cc base
    int by = blockIdx.y * 32;   // R base
    int tx = threadIdx.x, ty = threadIdx.y;
    #pragma unroll
    for (int i = 0; i < 32; i += 8)
        tile[ty + i][tx] = in[(size_t)(by + ty + i) * Cc + bx + tx];
    __syncthreads();
    #pragma unroll
    for (int i = 0; i < 32; i += 8)
        out[(size_t)(bx + ty + i) * R + by + tx] = to_tf32(tile[tx][ty + i]);
}

// ---------------------------------------------------------------------------
// TF32 tensor-core GEMM, cp.async double-buffered, BOTH operand fragments
// via ldmatrix. C = A(MxK) @ Bt^T (+bias); A [M][K], Bt [N][K].
// (identical to R13/R15 passing kernel)
// ---------------------------------------------------------------------------
template<bool HAS_BIAS, bool ROUND_OUT>
__global__ __launch_bounds__(256, 2)
void gemm_tf32_kernel(const float* __restrict__ A, const float* __restrict__ Bt,
                      const float* __restrict__ bias, float* __restrict__ Cmat,
                      int Mx, int Nx, int Kx)
{
    constexpr int BM = 128, BK = 32;
    constexpr int STR = 36;
    constexpr int TSZ = BM * STR;            // floats per tile buffer
    extern __shared__ float smem[];
    float* Asb[2] = { smem,           smem + TSZ };
    float* Bsb[2] = { smem + 2 * TSZ, smem + 3 * TSZ };

    const int tid  = threadIdx.x;
    const int lane = tid & 31;
    const int wid  = tid >> 5;
    const int wm   = wid >> 2;
    const int wn   = wid & 3;
    const int grp  = lane >> 2;
    const int qid  = lane & 3;
    const int bm = blockIdx.y * BM;
    const int bn = blockIdx.x * BM;

    const int a_lrow = ((lane >> 3) & 1) * 8 + (lane & 7);   // A-pattern row
    const int a_lcol = (lane >> 4) * 4;
    const int b_lrow = (lane >> 4) * 8 + (lane & 7);         // B-pattern row
    const int b_lcol = ((lane >> 3) & 1) * 4;

    const int g_row = tid >> 3, g_k4 = (tid & 7) * 4;        // cp.async coords

    const float* Aptr = A  + (size_t)(bm + g_row) * Kx + g_k4;
    const float* Bptr = Bt + (size_t)(bn + g_row) * Kx + g_k4;

    uint32_t sA[2], sB[2], uA[2], uB[2];
    #pragma unroll
    for (int b_ = 0; b_ < 2; b_++) {
        sA[b_] = (uint32_t)__cvta_generic_to_shared(Asb[b_] + g_row * STR + g_k4);
        sB[b_] = (uint32_t)__cvta_generic_to_shared(Bsb[b_] + g_row * STR + g_k4);
        uA[b_] = (uint32_t)__cvta_generic_to_shared(Asb[b_]);
        uB[b_] = (uint32_t)__cvta_generic_to_shared(Bsb[b_]);
    }

    const int ntiles = Kx / BK;

    auto issue = [&](int kt, int buf) {
        const float* Ag = Aptr + kt * BK;
        const float* Bg = Bptr + kt * BK;
        #pragma unroll
        for (int t = 0; t < 4; t++) {
            cp_async16(sA[buf] + t * (32 * STR * 4), Ag + (size_t)(t * 32) * Kx);
            cp_async16(sB[buf] + t * (32 * STR * 4), Bg + (size_t)(t * 32) * Kx);
        }
        cp_commit();
    };

    float acc[4][4][4];
    #pragma unroll
    for (int i = 0; i < 4; i++)
        #pragma unroll
        for (int j = 0; j < 4; j++)
            #pragma unroll
            for (int c = 0; c < 4; c++) acc[i][j][c] = 0.f;

    issue(0, 0);

    for (int kt = 0; kt < ntiles; kt++) {
        cp_wait0();
        __syncthreads();
        if (kt + 1 < ntiles) issue(kt + 1, (kt + 1) & 1);

        const int buf = kt & 1;
        const uint32_t uAb = uA[buf];
        const uint32_t uBb = uB[buf];
        #pragma unroll
        for (int s = 0; s < 4; s++) {
            const int k0 = s * 8;
            uint32_t afr[4][4];
            #pragma unroll
            for (int mt = 0; mt < 4; mt++)
                ldsm_x4(afr[mt], uAb + (uint32_t)(((wm * 64 + mt * 16 + a_lrow) * STR + k0 + a_lcol) * 4));
            #pragma unroll
            for (int p = 0; p < 2; p++) {
                uint32_t bfr[4];
                ldsm_x4(bfr, uBb + (uint32_t)(((wn * 32 + p * 16 + b_lrow) * STR + k0 + b_lcol) * 4));
                #pragma unroll
                for (int mt = 0; mt < 4; mt++) {
                    mma_tf32(acc[mt][2 * p    ], afr[mt], bfr[0], bfr[1]);
                    mma_tf32(acc[mt][2 * p + 1], afr[mt], bfr[2], bfr[3]);
                }
            }
        }
    }

    #pragma unroll
    for (int mt = 0; mt < 4; mt++) {
        #pragma unroll
        for (int nt = 0; nt < 4; nt++) {
            int row = bm + wm * 64 + mt * 16 + grp;
            int col = bn + wn * 32 + nt * 8 + qid * 2;
            float2 v0 = make_float2(acc[mt][nt][0], acc[mt][nt][1]);
            float2 v1 = make_float2(acc[mt][nt][2], acc[mt][nt][3]);
            if (HAS_BIAS) {
                float2 bb = *(const float2*)&bias[col];
                v0.x += bb.x; v0.y += bb.y;
                v1.x += bb.x; v1.y += bb.y;
            }
            if (ROUND_OUT) {
                v0.x = to_tf32(v0.x); v0.y = to_tf32(v0.y);
                v1.x = to_tf32(v1.x); v1.y = to_tf32(v1.y);
            }
            *(float2*)&Cmat[(size_t)row * Nx + col]       = v0;
            *(float2*)&Cmat[(size_t)(row + 8) * Nx + col] = v1;
        }
    }
}

// ---------------------------------------------------------------------------
// MMA flash-attention (tf32, causal), 128-query tiles, 8 warps,
// K-tiles of 32, 2 CTAs/SM. K double-buffered via cp.async.
// V now stored TRANSPOSED in smem (Vt[d][j], stride 36): loaded via LDG into
// registers one tile ahead, written with 8 scalar STS at tile start (buffer
// provably free), consumed by LDSM B-pattern fragments (16 LDSM replace the
// 64 scalar LDS of R15). Fragment values + MMA order bit-identical to R15.
// ---------------------------------------------------------------------------
__global__ __launch_bounds__(256, 2)
void attn_mma_kernel(const float* __restrict__ qkv, float* __restrict__ y)
{
    constexpr int STR  = 68;   // Q/K row stride (64 + 4 pad)
    constexpr int VSTR = 36;   // Vt row stride (32 + 4 pad)
    constexpr int PSTR = 36;   // P row stride (32 + 4 pad)
    constexpr int KT   = 32;   // K-tile rows
    extern __shared__ float sm[];
    float* Qs  = sm;                     // [128 q][68]
    float* Ksb = Qs  + 128 * STR;        // [2][32 j][68]
    float* Vtb = Ksb + 2 * KT * STR;     // [2][64 d][36]  (transposed V)
    float* Ps  = Vtb + 2 * 64 * VSTR;    // [8 warps][16 r][36]

    const int tid  = threadIdx.x;
    const int lane = tid & 31;
    const int w    = tid >> 5;
    const int grp  = lane >> 2;
    const int qid  = lane & 3;
    const int qt   = (int)gridDim.x - 1 - (int)blockIdx.x;  // longest first
    const int bh   = blockIdx.y;
    const int b    = bh >> 4;
    const int h    = bh & 15;
    // 1/sqrt(64) * log2(e): softmax uses ex2 directly
    const float qscale = 0.125f * 1.44269504088896340736f;

    const int a_lrow = ((lane >> 3) & 1) * 8 + (lane & 7);
    const int a_lcol = (lane >> 4) * 4;
    const int b_lrow = (lane >> 4) * 8 + (lane & 7);
    const int b_lcol = ((lane >> 3) & 1) * 4;

    const float* qbase = qkv + (size_t)(b * SEQ) * (3 * CH) + h * HD;
    const float* kbase = qbase + CH;
    const float* vbase = qbase + 2 * CH;

    float* Pw = Ps + w * 16 * PSTR;
    const uint32_t uQ  = (uint32_t)__cvta_generic_to_shared(Qs);
    const uint32_t uKs = (uint32_t)__cvta_generic_to_shared(Ksb);
    const uint32_t uVt = (uint32_t)__cvta_generic_to_shared(Vtb);
    const uint32_t uP  = (uint32_t)__cvta_generic_to_shared(Pw);

    // Load Q tile 128x64 into smem (pre-scaled), hoist A-frags to registers.
    #pragma unroll
    for (int t = 0; t < 8; t++) {
        int f   = tid + t * 256;
        int row = f >> 4;
        int c4  = (f & 15) * 4;
        float4 v = *(const float4*)&qbase[(size_t)(qt * 128 + row) * (3 * CH) + c4];
        v.x *= qscale; v.y *= qscale; v.z *= qscale; v.w *= qscale;
        *(float4*)&Qs[row * STR + c4] = v;
    }
    __syncthreads();
    uint32_t qfr[8][4];
    #pragma unroll
    for (int s = 0; s < 8; s++)
        ldsm_x4(qfr[s], uQ + (uint32_t)(((16 * w + a_lrow) * STR + s * 8 + a_lcol) * 4));

    // K tile: cp.async (32 rows x 64 floats); V tile: LDG prefetch -> STS.
    const int ld_row = tid >> 4;            // 0..15 (+16 second half)
    const int ld_c4  = (tid & 15) * 4;
    auto issueK = [&](int kt, int buf) {
        const float* Kg = kbase + (size_t)(kt * KT + ld_row) * (3 * CH) + ld_c4;
        uint32_t dK = uKs + (uint32_t)((buf * KT + ld_row) * STR + ld_c4) * 4;
        cp_async16(dK,                Kg);
        cp_async16(dK + 16 * STR * 4, Kg + (size_t)16 * (3 * CH));
        cp_commit();
    };
    // V prefetch coords: thread covers j = ld_row, ld_row+16; d = ld_c4..+3
    float4 vA, vB;
    auto ldgV = [&](int kt) {
        const float* Vg = vbase + (size_t)(kt * KT + ld_row) * (3 * CH) + ld_c4;
        vA = *(const float4*)Vg;
        vB = *(const float4*)(Vg + (size_t)16 * (3 * CH));
    };
    auto stsV = [&](int buf) {
        float* dst = Vtb + buf * 64 * VSTR;
        dst[(ld_c4 + 0) * VSTR + ld_row] = vA.x;
        dst[(ld_c4 + 1) * VSTR + ld_row] = vA.y;
        dst[(ld_c4 + 2) * VSTR + ld_row] = vA.z;
        dst[(ld_c4 + 3) * VSTR + ld_row] = vA.w;
        dst[(ld_c4 + 0) * VSTR + ld_row + 16] = vB.x;
        dst[(ld_c4 + 1) * VSTR + ld_row + 16] = vB.y;
        dst[(ld_c4 + 2) * VSTR + ld_row + 16] = vB.z;
        dst[(ld_c4 + 3) * VSTR + ld_row + 16] = vB.w;
    };

    float o[8][4];
    #pragma unroll
    for (int nt = 0; nt < 8; nt++)
        #pragma unroll
        for (int c = 0; c < 4; c++) o[nt][c] = 0.f;
    float m0 = -1e30f, m1 = -1e30f, l0 = 0.f, l1 = 0.f;

    const int row0 = 16 * w + grp;
    const int gi0  = qt * 128 + row0;
    const int gi1  = gi0 + 8;

    const int last = 4 * qt + 3;
    ldgV(0);
    issueK(0, 0);

    for (int kt = 0; kt <= last; kt++) {
        const int buf = kt & 1;
        // Write prefetched V tile kt (buffer free: all warps passed the
        // kt-1 barrier, so kt-2's PV -- last reader -- is complete).
        stsV(buf);
        cp_wait0();
        __syncthreads();                 // K kt + all V writes visible
        if (kt < last) { ldgV(kt + 1); issueK(kt + 1, (kt + 1) & 1); }

        const uint32_t uKb  = uKs + (uint32_t)(buf * KT * STR) * 4;
        const uint32_t uVtb = uVt + (uint32_t)(buf * 64 * VSTR) * 4;

        // ---- S = Q @ K^T (log2-domain) : Q-frags from registers
        float sfr[4][4];
        #pragma unroll
        for (int nt = 0; nt < 4; nt++)
            #pragma unroll
            for (int c = 0; c < 4; c++) sfr[nt][c] = 0.f;

        #pragma unroll
        for (int s = 0; s < 8; s++) {
            const int k0 = s * 8;
            #pragma unroll
            for (int p = 0; p < 2; p++) {
                uint32_t kf[4];
                ldsm_x4(kf, uKb + (uint32_t)(((p * 16 + b_lrow) * STR + k0 + b_lcol) * 4));
                mma_tf32(sfr[2 * p    ], qfr[s], kf[0], kf[1]);
                mma_tf32(sfr[2 * p + 1], qfr[s], kf[2], kf[3]);
            }
        }

        // ---- causal mask
        if (kt >= 4 * qt) {
            #pragma unroll
            for (int nt = 0; nt < 4; nt++) {
                int j0 = kt * KT + nt * 8 + qid * 2;
                if (j0     > gi0) sfr[nt][0] = -1e30f;
                if (j0 + 1 > gi0) sfr[nt][1] = -1e30f;
                if (j0     > gi1) sfr[nt][2] = -1e30f;
                if (j0 + 1 > gi1) sfr[nt][3] = -1e30f;
            }
        }

        // ---- online softmax (base-2, ex2.approx)
        float mx0 = -1e30f, mx1 = -1e30f;
        #pragma unroll
        for (int nt = 0; nt < 4; nt++) {
            mx0 = fmaxf(mx0, fmaxf(sfr[nt][0], sfr[nt][1]));
            mx1 = fmaxf(mx1, fmaxf(sfr[nt][2], sfr[nt][3]));
        }
        #pragma unroll
        for (int off = 1; off <= 2; off <<= 1) {
            mx0 = fmaxf(mx0, __shfl_xor_sync(0xffffffffu, mx0, off));
            mx1 = fmaxf(mx1, __shfl_xor_sync(0xffffffffu, mx1, off));
        }
        float mnew0 = fmaxf(m0, mx0), mnew1 = fmaxf(m1, mx1);
        float alpha0 = exp2_approx(m0 - mnew0), alpha1 = exp2_approx(m1 - mnew1);
        float sum0 = 0.f, sum1 = 0.f;
        #pragma unroll
        for (int nt = 0; nt < 4; nt++) {
            sfr[nt][0] = exp2_approx(sfr[nt][0] - mnew0);
            sfr[nt][1] = exp2_approx(sfr[nt][1] - mnew0);
            sfr[nt][2] = exp2_approx(sfr[nt][2] - mnew1);
            sfr[nt][3] = exp2_approx(sfr[nt][3] - mnew1);
            sum0 += sfr[nt][0] + sfr[nt][1];
            sum1 += sfr[nt][2] + sfr[nt][3];
        }
        #pragma unroll
        for (int off = 1; off <= 2; off <<= 1) {
            sum0 += __shfl_xor_sync(0xffffffffu, sum0, off);
            sum1 += __shfl_xor_sync(0xffffffffu, sum1, off);
        }
        l0 = l0 * alpha0 + sum0;  m0 = mnew0;
        l1 = l1 * alpha1 + sum1;  m1 = mnew1;

        // ---- write P (tf32) to per-warp smem; rescale O
        #pragma unroll
        for (int nt = 0; nt < 4; nt++) {
            int cc = nt * 8 + qid * 2;
            float2 p0 = make_float2(to_tf32(sfr[nt][0]), to_tf32(sfr[nt][1]));
            float2 p1 = make_float2(to_tf32(sfr[nt][2]), to_tf32(sfr[nt][3]));
            *(float2*)&Pw[(grp    ) * PSTR + cc] = p0;
            *(float2*)&Pw[(grp + 8) * PSTR + cc] = p1;
        }
        #pragma unroll
        for (int nt = 0; nt < 8; nt++) {
            o[nt][0] *= alpha0; o[nt][1] *= alpha0;
            o[nt][2] *= alpha1; o[nt][3] *= alpha1;
        }
        __syncwarp();

        // ---- O += P @ V : LDSM B-frags from transposed Vt (16 LDSM total)
        #pragma unroll
        for (int s = 0; s < 4; s++) {
            const int k0 = s * 8;
            uint32_t pf[4];
            ldsm_x4(pf, uP + (uint32_t)((a_lrow * PSTR + k0 + a_lcol) * 4));
            #pragma unroll
            for (int p = 0; p < 4; p++) {
                uint32_t vf[4];
                ldsm_x4(vf, uVtb + (uint32_t)(((p * 16 + b_lrow) * VSTR + k0 + b_lcol) * 4));
                mma_tf32(o[2 * p    ], pf, vf[0], vf[1]);
                mma_tf32(o[2 * p + 1], pf, vf[2], vf[3]);
            }
        }
        __syncwarp();
    }

    // ---- normalize + write y (tf32-rounded, feeds tf32 GEMM2)
    float inv0 = 1.0f / l0, inv1 = 1.0f / l1;
    #pragma unroll
    for (int nt = 0; nt < 8; nt++) {
        int d = nt * 8 + qid * 2;
        float2 v0 = make_float2(to_tf32(o[nt][0] * inv0), to_tf32(o[nt][1] * inv0));
        float2 v1 = make_float2(to_tf32(o[nt][2] * inv1), to_tf32(o[nt][3] * inv1));
        *(float2*)&y[(size_t)(b * SEQ + gi0) * CH + h * HD + d] = v0;
        *(float2*)&y[(size_t)(b * SEQ + gi1) * CH + h * HD + d] = v1;
    }
}

// ---------------------------------------------------------------------------

static constexpr int GEMM_SMEM = (4 * 128 * 36) * 4;   // 73728 B
static constexpr int ATTN_SMEM =
    (128 * 68 + 2 * 32 * 68 + 2 * 64 * 36 + 8 * 16 * 36) * 4;  // 89088 B

extern "C" void kernel_launch(void* const* d_in, const int* in_sizes, int n_in,
                              void* d_out, int out_size)
{
    (void)in_sizes; (void)n_in; (void)out_size;
    const float* x     = (const float*)d_in[0];
    const float* w_qkv = (const float*)d_in[1];
    const float* w_out = (const float*)d_in[2];
    const float* b_out = (const float*)d_in[3];
    float* out = (float*)d_out;

    float *qkv, *y, *xc, *wqT, *woT;
    cudaGetSymbolAddress((void**)&qkv, g_qkv);
    cudaGetSymbolAddress((void**)&y,   g_y);
    cudaGetSymbolAddress((void**)&xc,  g_x);
    cudaGetSymbolAddress((void**)&wqT, g_wqT);
    cudaGetSymbolAddress((void**)&woT, g_woT);

    cudaFuncSetAttribute(gemm_tf32_kernel<false, true>,
                         cudaFuncAttributeMaxDynamicSharedMemorySize, GEMM_SMEM);
    cudaFuncSetAttribute(gemm_tf32_kernel<true, false>,
                         cudaFuncAttributeMaxDynamicSharedMemorySize, GEMM_SMEM);
    cudaFuncSetAttribute(attn_mma_kernel,
                         cudaFuncAttributeMaxDynamicSharedMemorySize, ATTN_SMEM);

    // 0) operand prep: tf32-round x; transpose + tf32-round weights to [N][K]
    cvt_tf32_kernel<<<(MROWS * CH / 4 + 255) / 256, 256>>>(
        (const float4*)x, (float4*)xc, MROWS * CH / 4);
    transpose_tf32_kernel<<<dim3(3 * CH / 32, CH / 32), dim3(32, 8)>>>(
        w_qkv, wqT, CH, 3 * CH);
    transpose_tf32_kernel<<<dim3(CH / 32, CH / 32), dim3(32, 8)>>>(
        w_out, woT, CH, CH);

    // 1) qkv = x @ w_qkv  (tf32 TC, all-LDSM), output tf32-rounded
    gemm_tf32_kernel<false, true><<<dim3(3 * CH / 128, MROWS / 128), 256, GEMM_SMEM>>>(
        xc, wqT, nullptr, qkv, MROWS, 3 * CH, CH);

    // 2) causal flash attention -> y (tf32 TC, transposed-V LDSM PV path)
    attn_mma_kernel<<<dim3(SEQ / 128, BATCH * NH), 256, ATTN_SMEM>>>(qkv, y);

    // 3) out = y @ w_out + b_out  (tf32 TC, all-LDSM), fp32 output
    gemm_tf32_kernel<true, false><<<dim3(CH / 128, MROWS / 128), 256, GEMM_SMEM>>>(
        y, woT, b_out, out, MROWS, CH, CH);
}